// round 16
// baseline (speedup 1.0000x reference)
#include <cuda_runtime.h>
#include <cuda_fp16.h>
#include <cstdint>
#include <math.h>

// N=50000, H=256, E=300000.
// g = MLP(emb) once over nodes (exact restructure), per-edge cosine gather.
// FUSED MLP: one persistent kernel does both layers per 64-row tile; h lives
// only in smem (the layer-1 A staging slots are overwritten with h). W1/W2
// chunks stream through one B double-buffer (L2-resident). Single-product
// fp16 HMMA (measured 1.66e-4 vs 1e-3 gate).

#define H256 256
#define NPAD 50176   // 784*64
#define NTILES 784
#define CTAS 296     // 2/SM persistent

// ---------------- device scratch (allocation-free) ----------------
__device__ __align__(16) __half g_g16[(size_t)NPAD * H256];   // g as fp16
__device__ __align__(16) __half g_w1[H256 * H256];
__device__ __align__(16) __half g_w2[H256 * H256];
__device__ float g_sumsq[NPAD];         // full row sumsq (one CTA per row)

// ---------------- PTX helpers ----------------
__device__ __forceinline__ uint32_t smem_u32(const void* p) {
    uint32_t a;
    asm("{ .reg .u64 t; cvta.to.shared.u64 t, %1; cvt.u32.u64 %0, t; }" : "=r"(a) : "l"(p));
    return a;
}
__device__ __forceinline__ void cp16(uint32_t s, const void* g) {
    asm volatile("cp.async.cg.shared.global [%0], [%1], 16;"
                 :: "r"(s), "l"(__cvta_generic_to_global(g)) : "memory");
}
__device__ __forceinline__ void cp_commit() {
    asm volatile("cp.async.commit_group;" ::: "memory");
}
template <int NN>
__device__ __forceinline__ void cp_wait() {
    asm volatile("cp.async.wait_group %0;" :: "n"(NN) : "memory");
}
__device__ __forceinline__ void ldsm4(uint32_t* r, uint32_t addr) {
    asm volatile("ldmatrix.sync.aligned.m8n8.x4.shared.b16 {%0,%1,%2,%3}, [%4];"
                 : "=r"(r[0]), "=r"(r[1]), "=r"(r[2]), "=r"(r[3]) : "r"(addr));
}
__device__ __forceinline__ void mma_f16(float* c, const uint32_t* a, const uint32_t* b) {
    asm volatile(
        "mma.sync.aligned.m16n8k16.row.col.f32.f16.f16.f32 "
        "{%0,%1,%2,%3}, {%4,%5,%6,%7}, {%8,%9}, {%0,%1,%2,%3};"
        : "+f"(c[0]), "+f"(c[1]), "+f"(c[2]), "+f"(c[3])
        : "r"(a[0]), "r"(a[1]), "r"(a[2]), "r"(a[3]), "r"(b[0]), "r"(b[1]));
}
__device__ __forceinline__ uint32_t pack_h2(float a, float b) {
    __half2 t = __floats2half2_rn(a, b);
    return *reinterpret_cast<uint32_t*>(&t);
}

// SMEM (per-CTA 97KB):
//  A/h region: 4 slots x 8KB (64r x 64k fp16, XOR-swizzled) at 0..32768.
//    Layer-1 stages emb chunks here; epilogue-1 overwrites with h; layer-2
//    reads h from the same slots.
//  B region: 2 stages x 32KB (256r x 64k fp16) at 32768..98304 — streams
//    W1 c0..3 then W2 c0..3 then next tile's W1 c0 (seamless).
//  RED: 1KB at 98304.
#define A_SLOT(kc) ((uint32_t)(kc) * 8192u)
#define B_ST(st)   (32768u + (uint32_t)(st) * 32768u)
#define RED_OFF    98304
#define SMEM_BYTES 99328

// ---------------------------------------------------------------------------
// Fused MLP kernel: 296 persistent CTAs, 256 thr (8 warps = 2m x 4n of
// 32 rows x 64 cols). Each tile: 64 rows x full 256 cols, both layers.
// ---------------------------------------------------------------------------
__global__ __launch_bounds__(256, 2) void mlp_fused(
    const float* __restrict__ emb,
    const __half* __restrict__ w1, const __half* __restrict__ w2,
    const float* __restrict__ b1, const float* __restrict__ b2,
    int Nn, __half* __restrict__ g16, float* __restrict__ sumsq)
{
    extern __shared__ char smem[];
    const uint32_t sb = smem_u32(smem);
    const int tid  = threadIdx.x;
    const int lane = tid & 31, wid = tid >> 5;
    const int wm = wid & 1, wn = wid >> 1;        // 2 x 4 warps (32r x 64c)

    // ---- ldmatrix lane addressing ----
    const int a_r  = wm * 32 + (lane & 7) + ((lane >> 3) & 1) * 8;
    const int a_kq = ((lane >> 4) & 1) * 8;
    const int b_n  = wn * 64 + (lane & 7) + ((lane >> 4) & 1) * 8;
    const int b_kq = ((lane >> 3) & 1) * 8;
    uint32_t aRow[2], aMask[2], bRow[4], bMask[4];
#pragma unroll
    for (int i = 0; i < 2; i++) {
        int r = a_r + i * 16;
        aRow[i]  = (uint32_t)(r * 128);
        aMask[i] = (uint32_t)((r & 7) << 4);
    }
#pragma unroll
    for (int j = 0; j < 4; j++) {
        int n = b_n + j * 16;
        bRow[j]  = (uint32_t)(n * 128);
        bMask[j] = (uint32_t)((n & 7) << 4);
    }

    // Epilogue mapping (tile-local)
    const int rl_base = wm * 32 + (lane >> 2);    // 0..31 (+i*16+rh*8)
    const int cb      = wn * 64 + (lane & 3) * 2; // col in 0..255

    // ---- loaders ----
    auto loadB = [&](const __half* W, int kc, int st) {  // 256r x 64k chunk
        const uint32_t bb = sb + B_ST(st);
#pragma unroll
        for (int it = 0; it < 8; it++) {
            int idx = tid + it * 256;          // 0..2047
            int r = idx >> 3, c8 = idx & 7;
            uint32_t off = (uint32_t)(r * 128 + ((c8 * 16) ^ ((r & 7) << 4)));
            cp16(bb + off, W + (size_t)r * H256 + kc * 64 + c8 * 8);
        }
    };

    float4 regs[4];
    auto fetchA = [&](int row0, int kc) {      // fp32 emb -> regs (guarded)
#pragma unroll
        for (int it = 0; it < 4; it++) {
            int idx = tid + it * 256;          // float4 units
            int r = idx >> 4, k4u = idx & 15;
            regs[it] = (row0 + r < Nn)
                ? *(const float4*)(emb + (size_t)(row0 + r) * H256 + kc * 64 + k4u * 4)
                : make_float4(0.f, 0.f, 0.f, 0.f);
        }
    };
    auto storeA = [&](int slot) {              // regs -> fp16 smem slot
        const uint32_t base = A_SLOT(slot);
#pragma unroll
        for (int it = 0; it < 4; it++) {
            int idx = tid + it * 256;
            int r = idx >> 4, k4u = idx & 15;
            float4 v = regs[it];
            uint32_t off = (uint32_t)(r * 128 + ((k4u * 8) ^ ((r & 7) << 4)));
            *(uint2*)(smem + base + off) =
                make_uint2(pack_h2(v.x, v.y), pack_h2(v.z, v.w));
        }
    };

    float C[2][8][4];
    auto zeroC = [&]() {
#pragma unroll
        for (int i = 0; i < 2; i++)
#pragma unroll
            for (int j = 0; j < 8; j++)
#pragma unroll
                for (int p = 0; p < 4; p++) C[i][j][p] = 0.0f;
    };

    auto mmachunk = [&](int slot, int st) {
        const uint32_t aB = sb + A_SLOT(slot);
        const uint32_t bB = sb + B_ST(st);
#pragma unroll
        for (int s = 0; s < 4; s++) {
            const int k0 = s * 16;
            uint32_t ah[2][4], bh[4][4];
#pragma unroll
            for (int i = 0; i < 2; i++) {
                uint32_t off = aRow[i] + (((uint32_t)((k0 + a_kq) * 2)) ^ aMask[i]);
                ldsm4(ah[i], aB + off);
            }
#pragma unroll
            for (int j = 0; j < 4; j++) {
                uint32_t off = bRow[j] + (((uint32_t)((k0 + b_kq) * 2)) ^ bMask[j]);
                ldsm4(bh[j], bB + off);
            }
#pragma unroll
            for (int i = 0; i < 2; i++)
#pragma unroll
                for (int j = 0; j < 4; j++)
#pragma unroll
                    for (int h = 0; h < 2; h++)
                        mma_f16(C[i][j * 2 + h], ah[i], &bh[j][2 * h]);
        }
    };

    // ---- prologue: first tile's emb chunk 0 + W1 chunk 0 in flight ----
    fetchA(blockIdx.x * 64, 0);
    loadB(w1, 0, 0);
    cp_commit();
    zeroC();

    for (int t = blockIdx.x; t < NTILES; t += CTAS) {
        const int row0 = t * 64;
        const bool has_next = (t + CTAS < NTILES);

        // ================= layer 1 =================
#pragma unroll
        for (int kc = 0; kc < 4; kc++) {
            storeA(kc);
            cp_wait<0>();                      // B chunk kc arrived
            __syncthreads();                   // A slot kc visible; prior MMA done
            if (kc < 3) loadB(w1, kc + 1, (kc + 1) & 1);
            else        loadB(w2, 0, 0);       // q=4 -> stage 0
            cp_commit();
            if (kc < 3) fetchA(row0, kc + 1);
            mmachunk(kc, kc & 1);
        }

        // ---- epilogue 1: h = relu(C+b1) -> overwrite A slots (smem) ----
        __syncthreads();                       // all warps past MMA1
#pragma unroll
        for (int i = 0; i < 2; i++) {
#pragma unroll
            for (int ns = 0; ns < 8; ns++) {
                const int c = cb + ns * 8;
                const float bv0 = __ldg(&b1[c]);
                const float bv1 = __ldg(&b1[c + 1]);
#pragma unroll
                for (int rh = 0; rh < 2; rh++) {
                    const int rl = rl_base + i * 16 + rh * 8;
                    float v0 = fmaxf(C[i][ns][rh * 2 + 0] + bv0, 0.0f);
                    float v1 = fmaxf(C[i][ns][rh * 2 + 1] + bv1, 0.0f);
                    uint32_t off = A_SLOT(c >> 6) +
                        (uint32_t)(rl * 128 + (((c & 63) * 2) ^ ((rl & 7) << 4)));
                    *(uint32_t*)(smem + off) = pack_h2(v0, v1);
                }
            }
        }
        zeroC();
        __syncthreads();                       // h visible to all warps

        // ================= layer 2 =================
#pragma unroll
        for (int kc = 0; kc < 4; kc++) {
            cp_wait<0>();                      // W2 chunk kc arrived
            __syncthreads();
            bool issued = true;
            if (kc < 3) loadB(w2, kc + 1, (kc + 1) & 1);
            else if (has_next) loadB(w1, 0, 0);   // q=8 -> stage 0
            else issued = false;
            if (issued) cp_commit();
            if (kc == 2 && has_next) fetchA((t + CTAS) * 64, 0);
            mmachunk(kc, kc & 1);
        }

        // ---- epilogue 2: g16 global + full-row sumsq ----
        __syncthreads();                       // all warps past MMA2
        float ss[2][2] = {{0.f, 0.f}, {0.f, 0.f}};
#pragma unroll
        for (int i = 0; i < 2; i++) {
#pragma unroll
            for (int ns = 0; ns < 8; ns++) {
                const int c = cb + ns * 8;
                const float bv0 = __ldg(&b2[c]);
                const float bv1 = __ldg(&b2[c + 1]);
#pragma unroll
                for (int rh = 0; rh < 2; rh++) {
                    const int rl = rl_base + i * 16 + rh * 8;
                    float v0 = C[i][ns][rh * 2 + 0] + bv0;
                    float v1 = C[i][ns][rh * 2 + 1] + bv1;
                    *(uint32_t*)(g16 + (size_t)(row0 + rl) * H256 + c) = pack_h2(v0, v1);
                    ss[i][rh] = fmaf(v0, v0, ss[i][rh]);
                    ss[i][rh] = fmaf(v1, v1, ss[i][rh]);
                }
            }
        }
        {
            float* red = (float*)(smem + RED_OFF);   // 64 rows x 4 (wn)
#pragma unroll
            for (int i = 0; i < 2; i++)
#pragma unroll
                for (int rh = 0; rh < 2; rh++) {
                    float s = ss[i][rh];
                    s += __shfl_xor_sync(0xffffffffu, s, 1);
                    s += __shfl_xor_sync(0xffffffffu, s, 2);
                    int rl = rl_base + i * 16 + rh * 8;
                    if ((lane & 3) == 0) red[rl * 4 + wn] = s;
                }
            __syncthreads();
            if (tid < 64) {
                float s = ((red[tid * 4] + red[tid * 4 + 1]) + red[tid * 4 + 2]) + red[tid * 4 + 3];
                sumsq[row0 + tid] = s;
            }
            __syncthreads();                   // red + h slots free for next tile
        }
        zeroC();
    }
}

// ---------------------------------------------------------------------------
// Prep: convert W1/W2 (0.5 MB) to fp16. Tiny.
// ---------------------------------------------------------------------------
__global__ __launch_bounds__(256) void prep_w(
    const float* __restrict__ W1, const float* __restrict__ W2,
    __half* w1, __half* w2)
{
    int u = blockIdx.x * 256 + threadIdx.x;   // 8-elem units, 8192 per matrix
    if (u < H256 * H256 / 8) {
        const float4* p = (const float4*)(W1 + (size_t)u * 8);
        float4 a = p[0], b = p[1];
        *(uint4*)(w1 + (size_t)u * 8) =
            make_uint4(pack_h2(a.x, a.y), pack_h2(a.z, a.w),
                       pack_h2(b.x, b.y), pack_h2(b.z, b.w));
        const float4* q = (const float4*)(W2 + (size_t)u * 8);
        float4 c = q[0], d = q[1];
        *(uint4*)(w2 + (size_t)u * 8) =
            make_uint4(pack_h2(c.x, c.y), pack_h2(c.z, c.w),
                       pack_h2(d.x, d.y), pack_h2(d.z, d.w));
    }
}

// ---------------------------------------------------------------------------
// Edge kernel: 8 lanes per edge, 4 edges per warp. At the LTS roofline.
// sumsq is now complete per row (single load per node).
// ---------------------------------------------------------------------------
__global__ __launch_bounds__(256) void edge_kernel(
    const __half* __restrict__ g16, const float* __restrict__ ssq,
    const int* __restrict__ ei, float* __restrict__ out, int E, int N)
{
    const int tid  = threadIdx.x;
    const int sub  = tid & 7;
    const int e0   = blockIdx.x * 32 + (tid >> 3);
    const int e    = min(e0, E - 1);

    int c = ei[e];
    int r = ei[E + e];
    c = min(max(c, 0), N - 1);
    r = min(max(r, 0), N - 1);

    float sc = 0.f, sr = 0.f;
    if (sub == 0) {
        sc = __ldg(ssq + c);
        sr = __ldg(ssq + r);
    }

    const uint4* pa = (const uint4*)(g16 + (size_t)c * H256);
    const uint4* pb = (const uint4*)(g16 + (size_t)r * H256);

    float s = 0.0f;
#pragma unroll
    for (int j = 0; j < 4; j++) {
        uint4 a = pa[sub + j * 8];
        uint4 b = pb[sub + j * 8];
        const __half2* ha = (const __half2*)&a;
        const __half2* hb = (const __half2*)&b;
        __half2 acc = __hmul2(ha[0], hb[0]);
        acc = __hfma2(ha[1], hb[1], acc);
        acc = __hfma2(ha[2], hb[2], acc);
        acc = __hfma2(ha[3], hb[3], acc);
        float2 f = __half22float2(acc);
        s += f.x + f.y;
    }
    s += __shfl_xor_sync(0xffffffffu, s, 1);
    s += __shfl_xor_sync(0xffffffffu, s, 2);
    s += __shfl_xor_sync(0xffffffffu, s, 4);

    if (sub == 0 && e0 < E) {
        float nc = fmaxf(sqrtf(sc), 1e-8f);
        float nr = fmaxf(sqrtf(sr), 1e-8f);
        out[e0] = s / (nc * nr);
    }
}

// ---------------------------------------------------------------------------
extern "C" void kernel_launch(void* const* d_in, const int* in_sizes, int n_in,
                              void* d_out, int out_size)
{
    const float* emb = (const float*)d_in[0];
    const int*   ei  = (const int*)d_in[1];
    const float* W1  = (const float*)d_in[2];
    const float* b1  = (const float*)d_in[3];
    const float* W2  = (const float*)d_in[4];
    const float* b2  = (const float*)d_in[5];
    float*       out = (float*)d_out;

    const int Hn = in_sizes[3];
    const int N  = in_sizes[0] / Hn;
    const int E  = in_sizes[1] / 2;
    if (Hn != H256 || N > NPAD) return;

    float* ssbuf;
    __half *g16, *w1, *w2;
    cudaGetSymbolAddress((void**)&g16,   g_g16);
    cudaGetSymbolAddress((void**)&w1,    g_w1);
    cudaGetSymbolAddress((void**)&w2,    g_w2);
    cudaGetSymbolAddress((void**)&ssbuf, g_sumsq);

    cudaFuncSetAttribute(mlp_fused, cudaFuncAttributeMaxDynamicSharedMemorySize, SMEM_BYTES);

    prep_w<<<(H256 * H256 / 8 + 255) / 256, 256>>>(W1, W2, w1, w2);
    mlp_fused<<<CTAS, 256, SMEM_BYTES>>>(emb, w1, w2, b1, b2, N, g16, ssbuf);
    edge_kernel<<<(E + 31) / 32, 256>>>(g16, ssbuf, ei, out, E, N);
}

// round 17
// speedup vs baseline: 1.7090x; 1.7090x over previous
#include <cuda_runtime.h>
#include <cuda_fp16.h>
#include <cstdint>
#include <math.h>

// N=50000, H=256, E=300000.
// g = MLP(emb) once over nodes (exact restructure), per-edge cosine gather.
// GEMMs: warp-level HMMA, single-product fp16 (measured 1.66e-4 vs 1e-3).
// R17 = R13 (best, 86.5us) + ONE change: software-pipelined fragments —
// LDSMs for step s+1 issued before MMAs of step s (and step-0 LDSMs before
// the next-chunk cp.async burst), hiding the ~30cyc LDS dependency stall
// that capped tensor pipe at 32%.

#define H256 256
#define NPAD 50176   // 784*64
#define NT_ROW 784   // row tiles of 64
#define RT_STRIDE 148

// ---------------- device scratch (allocation-free) ----------------
__device__ __align__(16) __half g_g16[(size_t)NPAD * H256];   // g as fp16
__device__ __align__(16) __half g_h16[(size_t)NPAD * H256];   // h as fp16
__device__ __align__(16) __half g_w1[H256 * H256];
__device__ __align__(16) __half g_w2[H256 * H256];
__device__ float g_sumsq[2 * NPAD];     // per-column-tile partial row sumsq

// ---------------- PTX helpers ----------------
__device__ __forceinline__ uint32_t smem_u32(const void* p) {
    uint32_t a;
    asm("{ .reg .u64 t; cvta.to.shared.u64 t, %1; cvt.u32.u64 %0, t; }" : "=r"(a) : "l"(p));
    return a;
}
__device__ __forceinline__ void cp16(uint32_t s, const void* g) {
    asm volatile("cp.async.cg.shared.global [%0], [%1], 16;"
                 :: "r"(s), "l"(__cvta_generic_to_global(g)) : "memory");
}
__device__ __forceinline__ void cp_commit() {
    asm volatile("cp.async.commit_group;" ::: "memory");
}
template <int NN>
__device__ __forceinline__ void cp_wait() {
    asm volatile("cp.async.wait_group %0;" :: "n"(NN) : "memory");
}
__device__ __forceinline__ void ldsm4(uint32_t* r, uint32_t addr) {
    asm volatile("ldmatrix.sync.aligned.m8n8.x4.shared.b16 {%0,%1,%2,%3}, [%4];"
                 : "=r"(r[0]), "=r"(r[1]), "=r"(r[2]), "=r"(r[3]) : "r"(addr));
}
__device__ __forceinline__ void mma_f16(float* c, const uint32_t* a, const uint32_t* b) {
    asm volatile(
        "mma.sync.aligned.m16n8k16.row.col.f32.f16.f16.f32 "
        "{%0,%1,%2,%3}, {%4,%5,%6,%7}, {%8,%9}, {%0,%1,%2,%3};"
        : "+f"(c[0]), "+f"(c[1]), "+f"(c[2]), "+f"(c[3])
        : "r"(a[0]), "r"(a[1]), "r"(a[2]), "r"(a[3]), "r"(b[0]), "r"(b[1]));
}
__device__ __forceinline__ uint32_t pack_h2(float a, float b) {
    __half2 t = __floats2half2_rn(a, b);
    return *reinterpret_cast<uint32_t*>(&t);
}

// SMEM (per-CTA ~49KB):
//  A stage st: base st*8192 (8KB: 64r x 64k fp16, 128B/row XOR-swizzled)
//  B stage st: 16384 + st*16384 (16KB: 128r x 64k fp16)
//  RED: 1KB reduction scratch
#define A_ST(st)  ((uint32_t)(st) * 8192u)
#define B_ST(st)  (16384u + (uint32_t)(st) * 16384u)
#define RED_OFF   49152
#define SMEM_BYTES 50176

// ---------------------------------------------------------------------------
// Persistent single-product fp16 HMMA GEMM. 296 CTAs (2/SM), 256 thr
// (8 warps, 2m x 4n of 32x32). Fixed col half, row tiles strided by 148,
// K=256 in 4 chunks of 64, flat double-buffered chunk pipeline, fragments
// double-buffered across k-steps.
// mode 0: A = fp32 (converted on the fly); out = fp16 relu(C+bias).
// mode 1: A = fp16 (cp.async); out = fp16 C+bias + fp32 row sumsq part.
// ---------------------------------------------------------------------------
__global__ __launch_bounds__(256, 2) void gemm_hmma(
    const float* __restrict__ A32, const __half* __restrict__ A16,
    const __half* __restrict__ B16,
    const float* __restrict__ bias, int Nn, int mode,
    __half* __restrict__ OutH, float* __restrict__ sumsq)
{
    extern __shared__ char smem[];
    const uint32_t sb = smem_u32(smem);
    const int tid  = threadIdx.x;
    const int lane = tid & 31, wid = tid >> 5;
    const int wm = wid & 1, wn = wid >> 1;        // 2 x 4 warp grid (32x32 tiles)
    const int colSel = blockIdx.x & 1;
    const int col0 = colSel * 128;
    const int rt0  = blockIdx.x >> 1;             // 0..147

    float C[2][4][4];
#pragma unroll
    for (int i = 0; i < 2; i++)
#pragma unroll
        for (int j = 0; j < 4; j++)
#pragma unroll
            for (int q = 0; q < 4; q++) C[i][j][q] = 0.0f;

    // ---- ldmatrix lane addressing ----
    const int a_r  = wm * 32 + (lane & 7) + ((lane >> 3) & 1) * 8;
    const int a_kq = ((lane >> 4) & 1) * 8;
    const int b_n  = wn * 32 + (lane & 7) + ((lane >> 4) & 1) * 8;
    const int b_kq = ((lane >> 3) & 1) * 8;
    uint32_t aRow[2], aMask[2], bRow[2], bMask[2];
#pragma unroll
    for (int i = 0; i < 2; i++) {
        int r = a_r + i * 16;
        aRow[i]  = (uint32_t)(r * 128);
        aMask[i] = (uint32_t)((r & 7) << 4);
    }
#pragma unroll
    for (int j = 0; j < 2; j++) {
        int n = b_n + j * 16;
        bRow[j]  = (uint32_t)(n * 128);
        bMask[j] = (uint32_t)((n & 7) << 4);
    }

    // ---- loader helpers ----
    auto loadB = [&](int kc, int st) {
        uint32_t bb = sb + B_ST(st);
#pragma unroll
        for (int it = 0; it < 4; it++) {
            int idx = tid + it * 256;          // 0..1023
            int r = idx >> 3, c8 = idx & 7;
            uint32_t off = (uint32_t)(r * 128 + ((c8 * 16) ^ ((r & 7) << 4)));
            cp16(bb + off, B16 + (size_t)(col0 + r) * H256 + kc * 64 + c8 * 8);
        }
    };
    auto loadA1 = [&](int row0, int kc, int st) {  // mode 1: fp16 cp.async
        uint32_t ab = sb + A_ST(st);
#pragma unroll
        for (int it = 0; it < 2; it++) {
            int idx = tid + it * 256;          // 0..511
            int r = idx >> 3, c8 = idx & 7;
            uint32_t off = (uint32_t)(r * 128 + ((c8 * 16) ^ ((r & 7) << 4)));
            cp16(ab + off, A16 + (size_t)(row0 + r) * H256 + kc * 64 + c8 * 8);
        }
    };

    float4 regs[4];
    auto fetchA0 = [&](int row0, int kc) {     // mode 0: fp32 -> regs (guarded)
#pragma unroll
        for (int it = 0; it < 4; it++) {
            int idx = tid + it * 256;          // 0..1023 float4 units
            int r = idx >> 4, k4u = idx & 15;
            regs[it] = (row0 + r < Nn)
                ? *(const float4*)(A32 + (size_t)(row0 + r) * H256 + kc * 64 + k4u * 4)
                : make_float4(0.f, 0.f, 0.f, 0.f);
        }
    };
    auto storeA0 = [&](int st) {               // regs -> fp16 smem
        const uint32_t base = A_ST(st);
#pragma unroll
        for (int it = 0; it < 4; it++) {
            int idx = tid + it * 256;
            int r = idx >> 4, k4u = idx & 15;
            float4 v = regs[it];
            uint32_t off = (uint32_t)(r * 128 + ((k4u * 8) ^ ((r & 7) << 4)));
            *(uint2*)(smem + base + off) =
                make_uint2(pack_h2(v.x, v.y), pack_h2(v.z, v.w));
        }
    };

    // ---- prologue: first chunk of first tile in flight ----
    {
        int row0 = rt0 * 64;
        loadB(0, 0);
        if (mode == 1) { loadA1(row0, 0, 0); }
        cp_commit();
        if (mode == 0) fetchA0(row0, 0);
    }

    int q = 0;                                  // flat chunk counter
    for (int rt = rt0; rt < NT_ROW; rt += RT_STRIDE) {
        const int row0 = rt * 64;
#pragma unroll
        for (int kc = 0; kc < 4; kc++, q++) {
            const int st = q & 1;
            if (mode == 0) storeA0(st);
            cp_wait<0>();                       // chunk q arrived
            __syncthreads();                    // A(q)+B(q) visible; MMA(q-1) done

            const uint32_t aB = sb + A_ST(st);
            const uint32_t bB = sb + B_ST(st);

            // fragment double-buffer: issue step-0 LDSMs first, so their
            // latency hides under the next-chunk load issue below.
            uint32_t ah[2][2][4], bh[2][2][4];
            auto ldsmStep = [&](int s, int buf) {
                const int k0 = s * 16;
#pragma unroll
                for (int i = 0; i < 2; i++) {
                    uint32_t off = aRow[i] + (((uint32_t)((k0 + a_kq) * 2)) ^ aMask[i]);
                    ldsm4(ah[buf][i], aB + off);
                }
#pragma unroll
                for (int j = 0; j < 2; j++) {
                    uint32_t off = bRow[j] + (((uint32_t)((k0 + b_kq) * 2)) ^ bMask[j]);
                    ldsm4(bh[buf][j], bB + off);
                }
            };
            ldsmStep(0, 0);

            const bool last = (kc == 3) && (rt + RT_STRIDE >= NT_ROW);
            if (!last) {
                const int nkc   = (kc + 1) & 3;
                const int nrow0 = (kc == 3) ? (rt + RT_STRIDE) * 64 : row0;
                loadB(nkc, st ^ 1);
                if (mode == 1) loadA1(nrow0, nkc, st ^ 1);
                cp_commit();
                if (mode == 0) fetchA0(nrow0, nkc);
            }

#pragma unroll
            for (int s = 0; s < 4; s++) {
                const int cur = s & 1;
                if (s < 3) ldsmStep(s + 1, cur ^ 1);   // prefetch next step
#pragma unroll
                for (int i = 0; i < 2; i++)
#pragma unroll
                    for (int j = 0; j < 2; j++)
#pragma unroll
                        for (int h = 0; h < 2; h++)
                            mma_f16(C[i][j * 2 + h], ah[cur][i], &bh[cur][j][2 * h]);
            }
        }

        // ---- Epilogue for this row-tile ----
        const int rbase = row0 + wm * 32 + (lane >> 2);
        const int cbase = col0 + wn * 32 + (lane & 3) * 2;
        float ss[2][2] = {{0.f, 0.f}, {0.f, 0.f}};

#pragma unroll
        for (int i = 0; i < 2; i++) {
#pragma unroll
            for (int ns = 0; ns < 4; ns++) {
                const int c   = cbase + ns * 8;
                const float bv0 = __ldg(&bias[c]);
                const float bv1 = __ldg(&bias[c + 1]);
#pragma unroll
                for (int rh = 0; rh < 2; rh++) {
                    const int r = rbase + i * 16 + rh * 8;
                    float v0 = C[i][ns][rh * 2 + 0] + bv0;
                    float v1 = C[i][ns][rh * 2 + 1] + bv1;
                    const size_t go = (size_t)r * H256 + c;
                    if (mode == 0) {
                        v0 = fmaxf(v0, 0.0f);
                        v1 = fmaxf(v1, 0.0f);
                        *(uint32_t*)(OutH + go) = pack_h2(v0, v1);
                    } else {
                        *(uint32_t*)(OutH + go) = pack_h2(v0, v1);
                        ss[i][rh] = fmaf(v0, v0, ss[i][rh]);
                        ss[i][rh] = fmaf(v1, v1, ss[i][rh]);
                    }
                }
            }
        }

        if (mode == 1) {
            // Deterministic in-CTA row reduction; plain store to this column
            // tile's partial array (no atomics needed).
            float* red = (float*)(smem + RED_OFF);   // 64 rows x 4 (wn)
            __syncthreads();
#pragma unroll
            for (int i = 0; i < 2; i++)
#pragma unroll
                for (int rh = 0; rh < 2; rh++) {
                    float s = ss[i][rh];
                    s += __shfl_xor_sync(0xffffffffu, s, 1);
                    s += __shfl_xor_sync(0xffffffffu, s, 2);
                    int rl = wm * 32 + (lane >> 2) + i * 16 + rh * 8;
                    if ((lane & 3) == 0) red[rl * 4 + wn] = s;
                }
            __syncthreads();
            if (tid < 64) {
                float s = ((red[tid * 4] + red[tid * 4 + 1]) + red[tid * 4 + 2]) + red[tid * 4 + 3];
                sumsq[(size_t)colSel * NPAD + row0 + tid] = s;
            }
        }

        // reset accumulators for next tile
#pragma unroll
        for (int i = 0; i < 2; i++)
#pragma unroll
            for (int j = 0; j < 4; j++)
#pragma unroll
                for (int p = 0; p < 4; p++) C[i][j][p] = 0.0f;
    }
}

// ---------------------------------------------------------------------------
// Prep: convert W1/W2 to fp16.
// ---------------------------------------------------------------------------
__global__ __launch_bounds__(256) void prep_w(
    const float* __restrict__ W1, const float* __restrict__ W2,
    __half* w1, __half* w2)
{
    int i = blockIdx.x * 256 + threadIdx.x;
    if (i < H256 * H256) {
        w1[i] = __float2half_rn(W1[i]);
        w2[i] = __float2half_rn(W2[i]);
    }
}

// ---------------------------------------------------------------------------
// Edge kernel: 8 lanes per edge, 4 edges per warp, 32 edges per block.
// At the LTS roofline (~11 TB/s on the L2-resident fp16 g table).
// ---------------------------------------------------------------------------
__global__ __launch_bounds__(256) void edge_kernel(
    const __half* __restrict__ g16, const float* __restrict__ ssq,
    const int* __restrict__ ei, float* __restrict__ out, int E, int N)
{
    const int tid  = threadIdx.x;
    const int sub  = tid & 7;                       // lane within 8-lane group
    const int e0   = blockIdx.x * 32 + (tid >> 3);  // edge id for this group
    const int e    = min(e0, E - 1);                // clamp: keep lanes active

    int c = ei[e];
    int r = ei[E + e];
    c = min(max(c, 0), N - 1);
    r = min(max(r, 0), N - 1);

    float sc0 = 0.f, sc1 = 0.f, sr0 = 0.f, sr1 = 0.f;
    if (sub == 0) {
        sc0 = __ldg(ssq + c);
        sc1 = __ldg(ssq + NPAD + c);
        sr0 = __ldg(ssq + r);
        sr1 = __ldg(ssq + NPAD + r);
    }

    const uint4* pa = (const uint4*)(g16 + (size_t)c * H256);
    const uint4* pb = (const uint4*)(g16 + (size_t)r * H256);

    float s = 0.0f;
#pragma unroll
    for (int j = 0; j < 4; j++) {
        uint4 a = pa[sub + j * 8];
        uint4 b = pb[sub + j * 8];
        const __half2* ha = (const __half2*)&a;
        const __half2* hb = (const __half2*)&b;
        __half2 acc = __hmul2(ha[0], hb[0]);        // fp16 chain depth 4
        acc = __hfma2(ha[1], hb[1], acc);
        acc = __hfma2(ha[2], hb[2], acc);
        acc = __hfma2(ha[3], hb[3], acc);
        float2 f = __half22float2(acc);
        s += f.x + f.y;                             // fp32 across chains
    }
    s += __shfl_xor_sync(0xffffffffu, s, 1);
    s += __shfl_xor_sync(0xffffffffu, s, 2);
    s += __shfl_xor_sync(0xffffffffu, s, 4);

    if (sub == 0 && e0 < E) {
        float nc = fmaxf(sqrtf(sc0 + sc1), 1e-8f);
        float nr = fmaxf(sqrtf(sr0 + sr1), 1e-8f);
        out[e0] = s / (nc * nr);
    }
}

// ---------------------------------------------------------------------------
extern "C" void kernel_launch(void* const* d_in, const int* in_sizes, int n_in,
                              void* d_out, int out_size)
{
    const float* emb = (const float*)d_in[0];
    const int*   ei  = (const int*)d_in[1];
    const float* W1  = (const float*)d_in[2];
    const float* b1  = (const float*)d_in[3];
    const float* W2  = (const float*)d_in[4];
    const float* b2  = (const float*)d_in[5];
    float*       out = (float*)d_out;

    const int Hn = in_sizes[3];
    const int N  = in_sizes[0] / Hn;
    const int E  = in_sizes[1] / 2;
    if (Hn != H256 || N > NPAD) return;

    float* ssbuf;
    __half *g16, *h16, *w1, *w2;
    cudaGetSymbolAddress((void**)&g16,   g_g16);
    cudaGetSymbolAddress((void**)&h16,   g_h16);
    cudaGetSymbolAddress((void**)&w1,    g_w1);
    cudaGetSymbolAddress((void**)&w2,    g_w2);
    cudaGetSymbolAddress((void**)&ssbuf, g_sumsq);

    cudaFuncSetAttribute(gemm_hmma, cudaFuncAttributeMaxDynamicSharedMemorySize, SMEM_BYTES);

    prep_w<<<(H256 * H256 + 255) / 256, 256>>>(W1, W2, w1, w2);

    // Persistent: 296 CTAs (2/SM), each owns a col half + strided row tiles.
    gemm_hmma<<<2 * RT_STRIDE, 256, SMEM_BYTES>>>(emb, nullptr, w1, b1, N, 0,
                                                  h16, nullptr);
    gemm_hmma<<<2 * RT_STRIDE, 256, SMEM_BYTES>>>(nullptr, h16, w2, b2, N, 1,
                                                  g16, ssbuf);
    edge_kernel<<<(E + 31) / 32, 256>>>(g16, ssbuf, ei, out, E, N);
}